// round 15
// baseline (speedup 1.0000x reference)
#include <cuda_runtime.h>
#include <cuda_fp16.h>
#include <math.h>
#include <stdint.h>

using f16 = __half;

// Problem constants
constexpr int TOKENS = 4 * 4096;   // 16384
constexpr int D      = 1024;
constexpr int DFF    = 4096;

// ---------------------------------------------------------------------------
// Static device scratch — activations fp16, residual path exact fp32
// ---------------------------------------------------------------------------
__device__ f16   g_tmp [(size_t)TOKENS * D];        // LN output (reused for LN2)
__device__ f16   g_qkv [(size_t)TOKENS * 3 * D];    // q|k|v per token
__device__ f16   g_attn[(size_t)TOKENS * D];        // attention output
__device__ float g_x2  [(size_t)TOKENS * D];        // x + attn@Wo + bo (exact fp32)
__device__ f16   g_ff  [(size_t)TOKENS * DFF];      // gelu(tmp@W1+b1)
__device__ f16   g_wqkv[(size_t)3 * D * D];         // [3D, D]  (N,K layout)
__device__ f16   g_wo  [(size_t)D * D];
__device__ f16   g_w1  [(size_t)DFF * D];
__device__ f16   g_w2  [(size_t)D * DFF];

// ---------------------------------------------------------------------------
// PTX helpers
// ---------------------------------------------------------------------------
__device__ __forceinline__ void ldsm4(uint32_t& r0, uint32_t& r1, uint32_t& r2,
                                      uint32_t& r3, const void* p) {
    uint32_t a = (uint32_t)__cvta_generic_to_shared(p);
    asm volatile("ldmatrix.sync.aligned.m8n8.x4.shared.b16 {%0,%1,%2,%3}, [%4];\n"
                 : "=r"(r0), "=r"(r1), "=r"(r2), "=r"(r3) : "r"(a));
}

__device__ __forceinline__ void mma16816(float c[4], uint32_t a0, uint32_t a1,
                                         uint32_t a2, uint32_t a3,
                                         uint32_t b0, uint32_t b1) {
    asm volatile(
        "mma.sync.aligned.m16n8k16.row.col.f32.f16.f16.f32 "
        "{%0,%1,%2,%3}, {%4,%5,%6,%7}, {%8,%9}, {%0,%1,%2,%3};\n"
        : "+f"(c[0]), "+f"(c[1]), "+f"(c[2]), "+f"(c[3])
        : "r"(a0), "r"(a1), "r"(a2), "r"(a3), "r"(b0), "r"(b1));
}

__device__ __forceinline__ void cpa16(const void* smem, const void* gmem) {
    uint32_t a = (uint32_t)__cvta_generic_to_shared(smem);
    asm volatile("cp.async.cg.shared.global [%0], [%1], 16;\n" :: "r"(a), "l"(gmem) : "memory");
}
#define CP_COMMIT() asm volatile("cp.async.commit_group;\n" ::: "memory")

// ---------------------------------------------------------------------------
// Fused weight transpose + fp32->fp16 convert for ALL weights (one launch).
// Segments: 0..3 = Wq,Wk,Wv,Wo (1024x1024 each, 1024 tiles each);
// 4 = W1 (K=1024,N=4096; 4096 tiles); 5 = W2 (K=4096,N=1024; 4096 tiles).
// ---------------------------------------------------------------------------
__global__ void __launch_bounds__(256) transpose_all(
    const float* __restrict__ Wq, const float* __restrict__ Wk,
    const float* __restrict__ Wv, const float* __restrict__ Wo,
    const float* __restrict__ W1, const float* __restrict__ W2,
    f16* __restrict__ wqkv, f16* __restrict__ wo,
    f16* __restrict__ w1, f16* __restrict__ w2) {
    const int t = blockIdx.x;
    const float* W; f16* Wt; int K, N, nb, kb;
    if (t < 4096) {                 // the four 1024x1024 weights
        const int seg = t >> 10, rem = t & 1023;
        nb = rem & 31; kb = rem >> 5; K = D; N = D;
        switch (seg) {
            case 0: W = Wq; Wt = wqkv; break;
            case 1: W = Wk; Wt = wqkv + (size_t)D * D; break;
            case 2: W = Wv; Wt = wqkv + (size_t)2 * D * D; break;
            default: W = Wo; Wt = wo; break;
        }
    } else if (t < 8192) {          // W1: [1024, 4096]
        const int rem = t - 4096;
        nb = rem & 127; kb = rem >> 7; K = D; N = DFF; W = W1; Wt = w1;
    } else {                        // W2: [4096, 1024]
        const int rem = t - 8192;
        nb = rem & 31; kb = rem >> 5; K = DFF; N = D; W = W2; Wt = w2;
    }
    __shared__ float tt[32][33];
    const int n0 = nb * 32, k0 = kb * 32;
    #pragma unroll
    for (int r = threadIdx.y; r < 32; r += 8)
        tt[r][threadIdx.x] = W[(size_t)(k0 + r) * N + n0 + threadIdx.x];
    __syncthreads();
    #pragma unroll
    for (int r = threadIdx.y; r < 32; r += 8)
        Wt[(size_t)(n0 + r) * K + k0 + threadIdx.x] = __float2half_rn(tt[threadIdx.x][r]);
}

// ---------------------------------------------------------------------------
// LayerNorm (fp32 in -> fp16 out), one block per row of 1024
// ---------------------------------------------------------------------------
__global__ void __launch_bounds__(256) ln_kernel(const float* __restrict__ x,
                                                 const float* __restrict__ g,
                                                 const float* __restrict__ b,
                                                 f16* __restrict__ out) {
    const int row = blockIdx.x;
    const int tid = threadIdx.x;
    const float4 v = reinterpret_cast<const float4*>(x + (size_t)row * D)[tid];
    float s  = v.x + v.y + v.z + v.w;
    float ss = v.x * v.x + v.y * v.y + v.z * v.z + v.w * v.w;
    #pragma unroll
    for (int o = 16; o; o >>= 1) {
        s  += __shfl_xor_sync(0xffffffffu, s, o);
        ss += __shfl_xor_sync(0xffffffffu, ss, o);
    }
    __shared__ float sh[16];
    const int warp = tid >> 5, lane = tid & 31;
    if (lane == 0) { sh[warp] = s; sh[warp + 8] = ss; }
    __syncthreads();
    float ts = 0.f, tss = 0.f;
    #pragma unroll
    for (int w = 0; w < 8; ++w) { ts += sh[w]; tss += sh[w + 8]; }
    const float mu = ts * (1.0f / D);
    const float var = tss * (1.0f / D) - mu * mu;
    const float rs = rsqrtf(var + 1e-5f);
    const float4 gg = reinterpret_cast<const float4*>(g)[tid];
    const float4 bb = reinterpret_cast<const float4*>(b)[tid];
    __half2* o2 = reinterpret_cast<__half2*>(out + (size_t)row * D);
    o2[tid * 2 + 0] = __floats2half2_rn((v.x - mu) * rs * gg.x + bb.x,
                                        (v.y - mu) * rs * gg.y + bb.y);
    o2[tid * 2 + 1] = __floats2half2_rn((v.z - mu) * rs * gg.z + bb.z,
                                        (v.w - mu) * rs * gg.w + bb.w);
}

// ---------------------------------------------------------------------------
// Per-token head-mixing attention (fp16 in -> fp16 out, fp32 math).
// ---------------------------------------------------------------------------
__global__ void __launch_bounds__(64) attn_kernel(const f16* __restrict__ qkv,
                                                  const float* __restrict__ unc,
                                                  f16* __restrict__ out) {
    const int tok = blockIdx.x;
    const int i = threadIdx.x;
    __shared__ float ks[16][64];
    __shared__ float vs[16][64];
    const f16* base = qkv + (size_t)tok * (3 * D);

    float qi[16];
    #pragma unroll
    for (int h = 0; h < 16; ++h) {
        ks[h][i] = __half2float(base[D + h * 64 + i]);
        vs[h][i] = __half2float(base[2 * D + h * 64 + i]);
        qi[h] = __half2float(base[h * 64 + i]);
    }
    float su = 0.f;
    #pragma unroll
    for (int h = 0; h < 16; ++h) su += unc[h];
    const float iscale = 1.0f / (8.0f * su);
    __syncthreads();

    float s[64];
    #pragma unroll
    for (int j = 0; j < 64; ++j) s[j] = 0.f;
    #pragma unroll
    for (int h = 0; h < 16; ++h) {
        const float qh = qi[h];
        const float4* kr = reinterpret_cast<const float4*>(&ks[h][0]);
        #pragma unroll
        for (int j4 = 0; j4 < 16; ++j4) {
            const float4 kv = kr[j4];
            s[j4 * 4 + 0] += qh * kv.x;
            s[j4 * 4 + 1] += qh * kv.y;
            s[j4 * 4 + 2] += qh * kv.z;
            s[j4 * 4 + 3] += qh * kv.w;
        }
    }
    float m = -1e30f;
    #pragma unroll
    for (int j = 0; j < 64; ++j) { s[j] *= iscale; m = fmaxf(m, s[j]); }
    float den = 0.f;
    #pragma unroll
    for (int j = 0; j < 64; ++j) { s[j] = expf(s[j] - m); den += s[j]; }
    const float dinv = 1.0f / den;

    f16* ob = out + (size_t)tok * D;
    #pragma unroll
    for (int h = 0; h < 16; ++h) {
        const float4* vr = reinterpret_cast<const float4*>(&vs[h][0]);
        float o = 0.f;
        #pragma unroll
        for (int j4 = 0; j4 < 16; ++j4) {
            const float4 vv = vr[j4];
            o += s[j4 * 4 + 0] * vv.x + s[j4 * 4 + 1] * vv.y +
                 s[j4 * 4 + 2] * vv.z + s[j4 * 4 + 3] * vv.w;
        }
        ob[h * 64 + i] = __float2half_rn(o * dinv);
    }
}

// ---------------------------------------------------------------------------
// PERSISTENT tiled FP16 GEMM (fp32 accum): C[M,N] = A[M,K] @ Bt[N,K]^T.
// Grid = 2 x SM_count CTAs; each loops over its tiles (kills wave
// quantization). Per tile: R13-validated mainloop — BM=128, BN=128, BK=32,
// 3-stage cp.async, one __syncthreads per k-step, ldmatrix.x4 + m16n8k16.
// A per-tile leading __syncthreads closes the cross-tile buffer-reuse race.
// EPI 0: out fp16 = C
// EPI 1: out fp32 = C + bias + res     (exact residual path)
// EPI 2: out fp16 = gelu(C + bias)     (exact erf gelu)
// ---------------------------------------------------------------------------
constexpr int BM = 128, BN = 128, BK = 32, PAD = 8, STG = 3;
constexpr int SROWH = BK + PAD;                 // halves per smem row (40)
constexpr int A_ELE = BM * SROWH;               // halves per A stage (5120)
constexpr int B_ELE = BN * SROWH;
constexpr size_t GEMM_SMEM = (size_t)STG * (A_ELE + B_ELE) * 2;  // 61440 B

template <int EPI>
__global__ void __launch_bounds__(256, 2) gemm_f16(
    const f16* __restrict__ A, const f16* __restrict__ Bt,
    const float* __restrict__ bias, const float* __restrict__ res,
    void* __restrict__ out, int M, int N, int K) {
    extern __shared__ f16 smh[];
    f16* As = smh;                    // [STG][BM][SROWH]
    f16* Bs = smh + STG * A_ELE;      // [STG][BN][SROWH]

    const int tid = threadIdx.x;
    const int lane = tid & 31;
    const int warp = tid >> 5;
    const int wr = warp >> 2;       // 0..1 (M)
    const int wc = warp & 3;        // 0..3 (N)

    // cp.async mapping: each thread loads one row-half (16 halves = 2x16B)
    const int lrow = tid >> 1;
    const int lch = (tid & 1) * 16;
    f16* AsRow = As + lrow * SROWH + lch;
    f16* BsRow = Bs + lrow * SROWH + lch;

    const int gx = N / BN;
    const int tiles = gx * (M / BM);
    const int KT = K / BK;

    for (int tile = blockIdx.x; tile < tiles; tile += gridDim.x) {
        const int bm = (tile / gx) * BM;
        const int bn = (tile % gx) * BN;
        const f16* Ag = A + (size_t)(bm + lrow) * K + lch;
        const f16* Bg = Bt + (size_t)(bn + lrow) * K + lch;

        float acc[4][4][4];
        #pragma unroll
        for (int i = 0; i < 4; ++i)
            #pragma unroll
            for (int j = 0; j < 4; ++j)
                #pragma unroll
                for (int k = 0; k < 4; ++k) acc[i][j][k] = 0.f;

        auto load_stage = [&](int buf, int kt) {
            const f16* a = Ag + kt * BK;
            f16* as = AsRow + buf * A_ELE;
            cpa16(as, a);
            cpa16(as + 8, a + 8);
            const f16* b = Bg + kt * BK;
            f16* bs = BsRow + buf * B_ELE;
            cpa16(bs, b);
            cpa16(bs + 8, b + 8);
        };

        // all warps must have finished computing on the previous tile's
        // buffers before we overwrite them
        __syncthreads();
        load_stage(0, 0); CP_COMMIT();
        load_stage(1, 1); CP_COMMIT();

        for (int kt = 0; kt < KT; ++kt) {
            const int buf = kt % 3;
            asm volatile("cp.async.wait_group 1;\n" ::: "memory");
            __syncthreads();

            const f16* Ab = As + (size_t)buf * A_ELE;
            const f16* Bb = Bs + (size_t)buf * B_ELE;
            #pragma unroll
            for (int kk = 0; kk < 2; ++kk) {     // two k16 chunks in BK=32
                uint32_t af[4][4];
                #pragma unroll
                for (int mi = 0; mi < 4; ++mi) {
                    const int r = wr * 64 + mi * 16 + (lane & 15);
                    const int c = kk * 16 + (lane >> 4) * 8;
                    ldsm4(af[mi][0], af[mi][1], af[mi][2], af[mi][3],
                          Ab + (size_t)r * SROWH + c);
                }
                uint32_t bfr[2][4];
                #pragma unroll
                for (int nj = 0; nj < 2; ++nj) {  // covers n-tiles 2nj, 2nj+1
                    const int l8 = lane & 7;
                    const int q = lane >> 3;      // 0..3
                    const int n = wc * 32 + nj * 16 + (q >> 1) * 8 + l8;
                    const int c = kk * 16 + (q & 1) * 8;
                    ldsm4(bfr[nj][0], bfr[nj][1], bfr[nj][2], bfr[nj][3],
                          Bb + (size_t)n * SROWH + c);
                }
                #pragma unroll
                for (int mi = 0; mi < 4; ++mi)
                    #pragma unroll
                    for (int ni = 0; ni < 4; ++ni)
                        mma16816(acc[mi][ni], af[mi][0], af[mi][1], af[mi][2], af[mi][3],
                                 bfr[ni >> 1][(ni & 1) * 2], bfr[ni >> 1][(ni & 1) * 2 + 1]);
            }

            if (kt + 2 < KT) {
                load_stage((kt + 2) % 3, kt + 2);
                CP_COMMIT();
            } else {
                CP_COMMIT();   // keep group accounting uniform for wait_group 1
            }
        }

        // Epilogue (registers + gmem only; no smem reads)
        #pragma unroll
        for (int mi = 0; mi < 4; ++mi) {
            #pragma unroll
            for (int ni = 0; ni < 4; ++ni) {
                const int row = bm + wr * 64 + mi * 16 + (lane >> 2);
                const int col = bn + wc * 32 + ni * 8 + (lane & 3) * 2;
                const float c0 = acc[mi][ni][0], c1 = acc[mi][ni][1];
                const float c2 = acc[mi][ni][2], c3 = acc[mi][ni][3];
                if (EPI == 0) {
                    f16* o = (f16*)out;
                    *(__half2*)(o + (size_t)row * N + col) = __floats2half2_rn(c0, c1);
                    *(__half2*)(o + (size_t)(row + 8) * N + col) = __floats2half2_rn(c2, c3);
                } else if (EPI == 1) {
                    const float bz0 = bias[col], bz1 = bias[col + 1];
                    const float* r0 = res + (size_t)row * N + col;
                    const float* r1 = res + (size_t)(row + 8) * N + col;
                    float* o = (float*)out;
                    *(float2*)(o + (size_t)row * N + col) =
                        make_float2(c0 + bz0 + r0[0], c1 + bz1 + r0[1]);
                    *(float2*)(o + (size_t)(row + 8) * N + col) =
                        make_float2(c2 + bz0 + r1[0], c3 + bz1 + r1[1]);
                } else {
                    const float bz0 = bias[col], bz1 = bias[col + 1];
                    auto gelu = [](float v) { return 0.5f * v * (1.0f + erff(v * 0.70710678118654752f)); };
                    f16* o = (f16*)out;
                    *(__half2*)(o + (size_t)row * N + col) =
                        __floats2half2_rn(gelu(c0 + bz0), gelu(c1 + bz1));
                    *(__half2*)(o + (size_t)(row + 8) * N + col) =
                        __floats2half2_rn(gelu(c2 + bz0), gelu(c3 + bz1));
                }
            }
        }
    }
}

// ---------------------------------------------------------------------------
// Launch
// ---------------------------------------------------------------------------
extern "C" void kernel_launch(void* const* d_in, const int* in_sizes, int n_in,
                              void* d_out, int out_size) {
    const float* x    = (const float*)d_in[0];
    const float* unc  = (const float*)d_in[1];
    const float* Wq   = (const float*)d_in[2];
    const float* Wk   = (const float*)d_in[3];
    const float* Wv   = (const float*)d_in[4];
    const float* Wo   = (const float*)d_in[5];
    const float* bo   = (const float*)d_in[6];
    const float* ln1g = (const float*)d_in[7];
    const float* ln1b = (const float*)d_in[8];
    const float* ln2g = (const float*)d_in[9];
    const float* ln2b = (const float*)d_in[10];
    const float* W1   = (const float*)d_in[11];
    const float* b1   = (const float*)d_in[12];
    const float* W2   = (const float*)d_in[13];
    const float* b2   = (const float*)d_in[14];

    f16 *tmp, *qkv, *attn, *ff, *wqkv, *wo, *w1, *w2;
    float* x2;
    cudaGetSymbolAddress((void**)&tmp, g_tmp);
    cudaGetSymbolAddress((void**)&qkv, g_qkv);
    cudaGetSymbolAddress((void**)&attn, g_attn);
    cudaGetSymbolAddress((void**)&x2, g_x2);
    cudaGetSymbolAddress((void**)&ff, g_ff);
    cudaGetSymbolAddress((void**)&wqkv, g_wqkv);
    cudaGetSymbolAddress((void**)&wo, g_wo);
    cudaGetSymbolAddress((void**)&w1, g_w1);
    cudaGetSymbolAddress((void**)&w2, g_w2);

    cudaFuncSetAttribute(gemm_f16<0>, cudaFuncAttributeMaxDynamicSharedMemorySize, (int)GEMM_SMEM);
    cudaFuncSetAttribute(gemm_f16<1>, cudaFuncAttributeMaxDynamicSharedMemorySize, (int)GEMM_SMEM);
    cudaFuncSetAttribute(gemm_f16<2>, cudaFuncAttributeMaxDynamicSharedMemorySize, (int)GEMM_SMEM);

    int nsm = 148;
    cudaDeviceGetAttribute(&nsm, cudaDevAttrMultiProcessorCount, 0);
    const int PGRID = 2 * nsm;   // 2 CTAs resident per SM

    // all weight transposes in one launch
    transpose_all<<<12288, dim3(32, 8)>>>(Wq, Wk, Wv, Wo, W1, W2, wqkv, wo, w1, w2);

    // tmp = LN1(x)
    ln_kernel<<<TOKENS, 256>>>(x, ln1g, ln1b, tmp);
    // qkv = tmp @ [Wq|Wk|Wv]
    gemm_f16<0><<<PGRID, 256, GEMM_SMEM>>>(
        tmp, wqkv, nullptr, nullptr, qkv, TOKENS, 3 * D, D);
    // per-token attention
    attn_kernel<<<TOKENS, 64>>>(qkv, unc, attn);
    // x2 = x + attn @ Wo + bo
    gemm_f16<1><<<PGRID, 256, GEMM_SMEM>>>(
        attn, wo, bo, x, x2, TOKENS, D, D);
    // tmp = LN2(x2)
    ln_kernel<<<TOKENS, 256>>>(x2, ln2g, ln2b, tmp);
    // ff = gelu(tmp @ W1 + b1)
    gemm_f16<2><<<PGRID, 256, GEMM_SMEM>>>(
        tmp, w1, b1, nullptr, ff, TOKENS, DFF, D);
    // out = x2 + ff @ W2 + b2
    gemm_f16<1><<<PGRID, 256, GEMM_SMEM>>>(
        ff, w2, b2, x2, (float*)d_out, TOKENS, D, DFF);
}

// round 16
// speedup vs baseline: 1.0680x; 1.0680x over previous
#include <cuda_runtime.h>
#include <cuda_fp16.h>
#include <math.h>
#include <stdint.h>

using f16 = __half;

// Problem constants
constexpr int TOKENS = 4 * 4096;   // 16384
constexpr int D      = 1024;
constexpr int DFF    = 4096;

// ---------------------------------------------------------------------------
// Static device scratch — activations fp16, residual path exact fp32
// ---------------------------------------------------------------------------
__device__ f16   g_tmp [(size_t)TOKENS * D];        // LN output (reused for LN2)
__device__ f16   g_qkv [(size_t)TOKENS * 3 * D];    // q|k|v per token
__device__ f16   g_attn[(size_t)TOKENS * D];        // attention output
__device__ float g_x2  [(size_t)TOKENS * D];        // x + attn@Wo + bo (exact fp32)
__device__ f16   g_ff  [(size_t)TOKENS * DFF];      // gelu(tmp@W1+b1)
__device__ f16   g_wqkv[(size_t)3 * D * D];         // [3D, D]  (N,K layout)
__device__ f16   g_wo  [(size_t)D * D];
__device__ f16   g_w1  [(size_t)DFF * D];
__device__ f16   g_w2  [(size_t)D * DFF];

// ---------------------------------------------------------------------------
// PTX helpers
// ---------------------------------------------------------------------------
__device__ __forceinline__ void ldsm4(uint32_t& r0, uint32_t& r1, uint32_t& r2,
                                      uint32_t& r3, const void* p) {
    uint32_t a = (uint32_t)__cvta_generic_to_shared(p);
    asm volatile("ldmatrix.sync.aligned.m8n8.x4.shared.b16 {%0,%1,%2,%3}, [%4];\n"
                 : "=r"(r0), "=r"(r1), "=r"(r2), "=r"(r3) : "r"(a));
}

__device__ __forceinline__ void ldsm4t(uint32_t& r0, uint32_t& r1, uint32_t& r2,
                                       uint32_t& r3, const void* p) {
    uint32_t a = (uint32_t)__cvta_generic_to_shared(p);
    asm volatile("ldmatrix.sync.aligned.m8n8.x4.trans.shared.b16 {%0,%1,%2,%3}, [%4];\n"
                 : "=r"(r0), "=r"(r1), "=r"(r2), "=r"(r3) : "r"(a));
}

__device__ __forceinline__ void mma16816(float c[4], uint32_t a0, uint32_t a1,
                                         uint32_t a2, uint32_t a3,
                                         uint32_t b0, uint32_t b1) {
    asm volatile(
        "mma.sync.aligned.m16n8k16.row.col.f32.f16.f16.f32 "
        "{%0,%1,%2,%3}, {%4,%5,%6,%7}, {%8,%9}, {%0,%1,%2,%3};\n"
        : "+f"(c[0]), "+f"(c[1]), "+f"(c[2]), "+f"(c[3])
        : "r"(a0), "r"(a1), "r"(a2), "r"(a3), "r"(b0), "r"(b1));
}

__device__ __forceinline__ void cpa16(const void* smem, const void* gmem) {
    uint32_t a = (uint32_t)__cvta_generic_to_shared(smem);
    asm volatile("cp.async.cg.shared.global [%0], [%1], 16;\n" :: "r"(a), "l"(gmem) : "memory");
}
#define CP_COMMIT() asm volatile("cp.async.commit_group;\n" ::: "memory")

__device__ __forceinline__ uint32_t h2u(float a, float b) {
    __half2 h = __floats2half2_rn(a, b);
    return *reinterpret_cast<uint32_t*>(&h);
}

// ---------------------------------------------------------------------------
// Fused weight transpose + fp32->fp16 convert for ALL weights (one launch).
// ---------------------------------------------------------------------------
__global__ void __launch_bounds__(256) transpose_all(
    const float* __restrict__ Wq, const float* __restrict__ Wk,
    const float* __restrict__ Wv, const float* __restrict__ Wo,
    const float* __restrict__ W1, const float* __restrict__ W2,
    f16* __restrict__ wqkv, f16* __restrict__ wo,
    f16* __restrict__ w1, f16* __restrict__ w2) {
    const int t = blockIdx.x;
    const float* W; f16* Wt; int K, N, nb, kb;
    if (t < 4096) {                 // the four 1024x1024 weights
        const int seg = t >> 10, rem = t & 1023;
        nb = rem & 31; kb = rem >> 5; K = D; N = D;
        switch (seg) {
            case 0: W = Wq; Wt = wqkv; break;
            case 1: W = Wk; Wt = wqkv + (size_t)D * D; break;
            case 2: W = Wv; Wt = wqkv + (size_t)2 * D * D; break;
            default: W = Wo; Wt = wo; break;
        }
    } else if (t < 8192) {          // W1: [1024, 4096]
        const int rem = t - 4096;
        nb = rem & 127; kb = rem >> 7; K = D; N = DFF; W = W1; Wt = w1;
    } else {                        // W2: [4096, 1024]
        const int rem = t - 8192;
        nb = rem & 31; kb = rem >> 5; K = DFF; N = D; W = W2; Wt = w2;
    }
    __shared__ float tt[32][33];
    const int n0 = nb * 32, k0 = kb * 32;
    #pragma unroll
    for (int r = threadIdx.y; r < 32; r += 8)
        tt[r][threadIdx.x] = W[(size_t)(k0 + r) * N + n0 + threadIdx.x];
    __syncthreads();
    #pragma unroll
    for (int r = threadIdx.y; r < 32; r += 8)
        Wt[(size_t)(n0 + r) * K + k0 + threadIdx.x] = __float2half_rn(tt[threadIdx.x][r]);
}

// ---------------------------------------------------------------------------
// LayerNorm (fp32 in -> fp16 out), one block per row of 1024
// ---------------------------------------------------------------------------
__global__ void __launch_bounds__(256) ln_kernel(const float* __restrict__ x,
                                                 const float* __restrict__ g,
                                                 const float* __restrict__ b,
                                                 f16* __restrict__ out) {
    const int row = blockIdx.x;
    const int tid = threadIdx.x;
    const float4 v = reinterpret_cast<const float4*>(x + (size_t)row * D)[tid];
    float s  = v.x + v.y + v.z + v.w;
    float ss = v.x * v.x + v.y * v.y + v.z * v.z + v.w * v.w;
    #pragma unroll
    for (int o = 16; o; o >>= 1) {
        s  += __shfl_xor_sync(0xffffffffu, s, o);
        ss += __shfl_xor_sync(0xffffffffu, ss, o);
    }
    __shared__ float sh[16];
    const int warp = tid >> 5, lane = tid & 31;
    if (lane == 0) { sh[warp] = s; sh[warp + 8] = ss; }
    __syncthreads();
    float ts = 0.f, tss = 0.f;
    #pragma unroll
    for (int w = 0; w < 8; ++w) { ts += sh[w]; tss += sh[w + 8]; }
    const float mu = ts * (1.0f / D);
    const float var = tss * (1.0f / D) - mu * mu;
    const float rs = rsqrtf(var + 1e-5f);
    const float4 gg = reinterpret_cast<const float4*>(g)[tid];
    const float4 bb = reinterpret_cast<const float4*>(b)[tid];
    __half2* o2 = reinterpret_cast<__half2*>(out + (size_t)row * D);
    o2[tid * 2 + 0] = __floats2half2_rn((v.x - mu) * rs * gg.x + bb.x,
                                        (v.y - mu) * rs * gg.y + bb.y);
    o2[tid * 2 + 1] = __floats2half2_rn((v.z - mu) * rs * gg.z + bb.z,
                                        (v.w - mu) * rs * gg.w + bb.w);
}

// ---------------------------------------------------------------------------
// Tensor-core per-token head-mixing attention.
// Per token: scores(64x64) = q(64x16) @ k(64x16)^T * iscale; P = softmax(rows);
// out(64x16) = P @ v(64x16)  [v stored [h][i] == B's [n][k] layout].
// CTA = 256 threads = 8 warps = 2 tokens; warp = 16-row slab of one token.
// Fragments: q,k via ldmatrix.x4.trans from [h][i] smem; V via non-trans;
// P converted C-frag -> A-frag purely in registers. fp32 softmax/accum.
// ---------------------------------------------------------------------------
constexpr int ASTR = 72;   // halves per smem row (144B: conflict-free ldmatrix)

__global__ void __launch_bounds__(256) attn_tc(const f16* __restrict__ qkv,
                                               const float* __restrict__ unc,
                                               f16* __restrict__ out) {
    __shared__ f16 smq[2][3][16 * ASTR];   // [token][q/k/v][h*ASTR + i]
    const int tid = threadIdx.x;
    const int warp = tid >> 5, lane = tid & 31;
    const int tw = warp >> 2;              // token within CTA (0..1)
    const int mi = warp & 3;               // slab: rows i0..i0+15
    const int i0 = mi * 16;
    const int tok0 = blockIdx.x * 2;
    const int lr = lane & 7, seg = lane >> 3;
    const int g = lane >> 2, t4 = lane & 3;

    // Stage q/k/v for both tokens: 2 x 384 16B-chunks
    #pragma unroll
    for (int it = 0; it < 3; ++it) {
        const int cc = tid + it * 256;           // 0..767
        const int token = cc >= 384;
        const int c = cc - token * 384;
        const int part = c >> 7;                  // 0..2
        const int rem = c & 127;
        const int h = rem >> 3, ic = rem & 7;
        cpa16(&smq[token][part][h * ASTR + ic * 8],
              qkv + (size_t)(tok0 + token) * (3 * D) + part * 1024 + h * 64 + ic * 8);
    }
    CP_COMMIT();
    asm volatile("cp.async.wait_group 0;\n" ::: "memory");

    float su = 0.f;
    #pragma unroll
    for (int h = 0; h < 16; ++h) su += unc[h];
    const float iscale = 1.0f / (8.0f * su);
    __syncthreads();

    // q A-frag (m16k16): trans tiles (i0-7,h0-7)(i8-15,h0-7)(i0-7,h8-15)(i8-15,h8-15)
    const f16* qb = smq[tw][0];
    uint32_t aq[4];
    {
        const int ah = lr + ((seg >= 2) ? 8 : 0);
        const int ai = i0 + ((seg & 1) ? 8 : 0);
        ldsm4t(aq[0], aq[1], aq[2], aq[3], qb + ah * ASTR + ai);
    }

    // scores: 8 n-tiles of 8 j-columns
    float acc[8][4];
    #pragma unroll
    for (int nt = 0; nt < 8; ++nt)
        #pragma unroll
        for (int e = 0; e < 4; ++e) acc[nt][e] = 0.f;

    const f16* kb = smq[tw][1];
    #pragma unroll
    for (int c = 0; c < 4; ++c) {
        // trans tiles: (j16c..+7,h0-7)->b0[2c]; (j16c..+7,h8-15)->b1[2c];
        //              (j16c+8..,h0-7)->b0[2c+1]; (j16c+8..,h8-15)->b1[2c+1]
        const int bh = lr + ((seg & 1) ? 8 : 0);
        const int bj = 16 * c + ((seg >> 1) ? 8 : 0);
        uint32_t kb4[4];
        ldsm4t(kb4[0], kb4[1], kb4[2], kb4[3], kb + bh * ASTR + bj);
        mma16816(acc[2 * c], aq[0], aq[1], aq[2], aq[3], kb4[0], kb4[1]);
        mma16816(acc[2 * c + 1], aq[0], aq[1], aq[2], aq[3], kb4[2], kb4[3]);
    }

    // softmax over rows i0+g (elements 0,1) and i0+8+g (elements 2,3)
    float m0 = -1e30f, m1 = -1e30f;
    #pragma unroll
    for (int nt = 0; nt < 8; ++nt) {
        #pragma unroll
        for (int e = 0; e < 4; ++e) acc[nt][e] *= iscale;
        m0 = fmaxf(m0, fmaxf(acc[nt][0], acc[nt][1]));
        m1 = fmaxf(m1, fmaxf(acc[nt][2], acc[nt][3]));
    }
    m0 = fmaxf(m0, __shfl_xor_sync(0xffffffffu, m0, 1));
    m0 = fmaxf(m0, __shfl_xor_sync(0xffffffffu, m0, 2));
    m1 = fmaxf(m1, __shfl_xor_sync(0xffffffffu, m1, 1));
    m1 = fmaxf(m1, __shfl_xor_sync(0xffffffffu, m1, 2));
    float s0 = 0.f, s1 = 0.f;
    #pragma unroll
    for (int nt = 0; nt < 8; ++nt) {
        acc[nt][0] = expf(acc[nt][0] - m0); s0 += acc[nt][0];
        acc[nt][1] = expf(acc[nt][1] - m0); s0 += acc[nt][1];
        acc[nt][2] = expf(acc[nt][2] - m1); s1 += acc[nt][2];
        acc[nt][3] = expf(acc[nt][3] - m1); s1 += acc[nt][3];
    }
    s0 += __shfl_xor_sync(0xffffffffu, s0, 1);
    s0 += __shfl_xor_sync(0xffffffffu, s0, 2);
    s1 += __shfl_xor_sync(0xffffffffu, s1, 1);
    s1 += __shfl_xor_sync(0xffffffffu, s1, 2);
    const float d0 = 1.0f / s0, d1 = 1.0f / s1;
    #pragma unroll
    for (int nt = 0; nt < 8; ++nt) {
        acc[nt][0] *= d0; acc[nt][1] *= d0;
        acc[nt][2] *= d1; acc[nt][3] *= d1;
    }

    // AV: A = P (C-frag == A-frag layout pairwise), B = V non-trans
    float oacc[2][4];
    #pragma unroll
    for (int nt = 0; nt < 2; ++nt)
        #pragma unroll
        for (int e = 0; e < 4; ++e) oacc[nt][e] = 0.f;

    const f16* vb = smq[tw][2];
    #pragma unroll
    for (int kt = 0; kt < 4; ++kt) {
        const uint32_t pa0 = h2u(acc[2 * kt][0], acc[2 * kt][1]);
        const uint32_t pa1 = h2u(acc[2 * kt][2], acc[2 * kt][3]);
        const uint32_t pa2 = h2u(acc[2 * kt + 1][0], acc[2 * kt + 1][1]);
        const uint32_t pa3 = h2u(acc[2 * kt + 1][2], acc[2 * kt + 1][3]);
        // V tiles (non-trans): (h0-7,j16kt)(h0-7,j+8)(h8-15,j16kt)(h8-15,j+8)
        const int vh = lr + ((seg >> 1) ? 8 : 0);
        const int vj = 16 * kt + ((seg & 1) ? 8 : 0);
        uint32_t vb4[4];
        ldsm4(vb4[0], vb4[1], vb4[2], vb4[3], vb + vh * ASTR + vj);
        mma16816(oacc[0], pa0, pa1, pa2, pa3, vb4[0], vb4[1]);
        mma16816(oacc[1], pa0, pa1, pa2, pa3, vb4[2], vb4[3]);
    }

    // Epilogue: out[tok][h*64 + i]
    f16* ob = out + (size_t)(tok0 + tw) * D;
    #pragma unroll
    for (int nt = 0; nt < 2; ++nt) {
        const int h0 = nt * 8 + 2 * t4;
        ob[h0 * 64 + i0 + g]           = __float2half_rn(oacc[nt][0]);
        ob[(h0 + 1) * 64 + i0 + g]     = __float2half_rn(oacc[nt][1]);
        ob[h0 * 64 + i0 + 8 + g]       = __float2half_rn(oacc[nt][2]);
        ob[(h0 + 1) * 64 + i0 + 8 + g] = __float2half_rn(oacc[nt][3]);
    }
}

// ---------------------------------------------------------------------------
// PERSISTENT tiled FP16 GEMM (fp32 accum): C[M,N] = A[M,K] @ Bt[N,K]^T.
// R13/R14-validated mainloop: BM=128, BN=128, BK=32, 3-stage cp.async, one
// __syncthreads per k-step, ldmatrix.x4 + m16n8k16.
// ---------------------------------------------------------------------------
constexpr int BM = 128, BN = 128, BK = 32, PAD = 8, STG = 3;
constexpr int SROWH = BK + PAD;
constexpr int A_ELE = BM * SROWH;
constexpr int B_ELE = BN * SROWH;
constexpr size_t GEMM_SMEM = (size_t)STG * (A_ELE + B_ELE) * 2;  // 61440 B

template <int EPI>
__global__ void __launch_bounds__(256, 2) gemm_f16(
    const f16* __restrict__ A, const f16* __restrict__ Bt,
    const float* __restrict__ bias, const float* __restrict__ res,
    void* __restrict__ out, int M, int N, int K) {
    extern __shared__ f16 smh[];
    f16* As = smh;
    f16* Bs = smh + STG * A_ELE;

    const int tid = threadIdx.x;
    const int lane = tid & 31;
    const int warp = tid >> 5;
    const int wr = warp >> 2;
    const int wc = warp & 3;

    const int lrow = tid >> 1;
    const int lch = (tid & 1) * 16;
    f16* AsRow = As + lrow * SROWH + lch;
    f16* BsRow = Bs + lrow * SROWH + lch;

    const int gx = N / BN;
    const int tiles = gx * (M / BM);
    const int KT = K / BK;

    for (int tile = blockIdx.x; tile < tiles; tile += gridDim.x) {
        const int bm = (tile / gx) * BM;
        const int bn = (tile % gx) * BN;
        const f16* Ag = A + (size_t)(bm + lrow) * K + lch;
        const f16* Bg = Bt + (size_t)(bn + lrow) * K + lch;

        float acc[4][4][4];
        #pragma unroll
        for (int i = 0; i < 4; ++i)
            #pragma unroll
            for (int j = 0; j < 4; ++j)
                #pragma unroll
                for (int k = 0; k < 4; ++k) acc[i][j][k] = 0.f;

        auto load_stage = [&](int buf, int kt) {
            const f16* a = Ag + kt * BK;
            f16* as = AsRow + buf * A_ELE;
            cpa16(as, a);
            cpa16(as + 8, a + 8);
            const f16* b = Bg + kt * BK;
            f16* bs = BsRow + buf * B_ELE;
            cpa16(bs, b);
            cpa16(bs + 8, b + 8);
        };

        __syncthreads();
        load_stage(0, 0); CP_COMMIT();
        load_stage(1, 1); CP_COMMIT();

        for (int kt = 0; kt < KT; ++kt) {
            const int buf = kt % 3;
            asm volatile("cp.async.wait_group 1;\n" ::: "memory");
            __syncthreads();

            const f16* Ab = As + (size_t)buf * A_ELE;
            const f16* Bb = Bs + (size_t)buf * B_ELE;
            #pragma unroll
            for (int kk = 0; kk < 2; ++kk) {
                uint32_t af[4][4];
                #pragma unroll
                for (int mi = 0; mi < 4; ++mi) {
                    const int r = wr * 64 + mi * 16 + (lane & 15);
                    const int c = kk * 16 + (lane >> 4) * 8;
                    ldsm4(af[mi][0], af[mi][1], af[mi][2], af[mi][3],
                          Ab + (size_t)r * SROWH + c);
                }
                uint32_t bfr[2][4];
                #pragma unroll
                for (int nj = 0; nj < 2; ++nj) {
                    const int l8 = lane & 7;
                    const int q = lane >> 3;
                    const int n = wc * 32 + nj * 16 + (q >> 1) * 8 + l8;
                    const int c = kk * 16 + (q & 1) * 8;
                    ldsm4(bfr[nj][0], bfr[nj][1], bfr[nj][2], bfr[nj][3],
                          Bb + (size_t)n * SROWH + c);
                }
                #pragma unroll
                for (int mi = 0; mi < 4; ++mi)
                    #pragma unroll
                    for (int ni = 0; ni < 4; ++ni)
                        mma16816(acc[mi][ni], af[mi][0], af[mi][1], af[mi][2], af[mi][3],
                                 bfr[ni >> 1][(ni & 1) * 2], bfr[ni >> 1][(ni & 1) * 2 + 1]);
            }

            if (kt + 2 < KT) {
                load_stage((kt + 2) % 3, kt + 2);
                CP_COMMIT();
            } else {
                CP_COMMIT();
            }
        }

        #pragma unroll
        for (int mi = 0; mi < 4; ++mi) {
            #pragma unroll
            for (int ni = 0; ni < 4; ++ni) {
                const int row = bm + wr * 64 + mi * 16 + (lane >> 2);
                const int col = bn + wc * 32 + ni * 8 + (lane & 3) * 2;
                const float c0 = acc[mi][ni][0], c1 = acc[mi][ni][1];
                const float c2 = acc[mi][ni][2], c3 = acc[mi][ni][3];
                if (EPI == 0) {
                    f16* o = (f16*)out;
                    *(__half2*)(o + (size_t)row * N + col) = __floats2half2_rn(c0, c1);
                    *(__half2*)(o + (size_t)(row + 8) * N + col) = __floats2half2_rn(c2, c3);
                } else if (EPI == 1) {
                    const float bz0 = bias[col], bz1 = bias[col + 1];
                    const float* r0 = res + (size_t)row * N + col;
                    const float* r1 = res + (size_t)(row + 8) * N + col;
                    float* o = (float*)out;
                    *(float2*)(o + (size_t)row * N + col) =
                        make_float2(c0 + bz0 + r0[0], c1 + bz1 + r0[1]);
                    *(float2*)(o + (size_t)(row + 8) * N + col) =
                        make_float2(c2 + bz0 + r1[0], c3 + bz1 + r1[1]);
                } else {
                    const float bz0 = bias[col], bz1 = bias[col + 1];
                    auto gelu = [](float v) { return 0.5f * v * (1.0f + erff(v * 0.70710678118654752f)); };
                    f16* o = (f16*)out;
                    *(__half2*)(o + (size_t)row * N + col) =
                        __floats2half2_rn(gelu(c0 + bz0), gelu(c1 + bz1));
                    *(__half2*)(o + (size_t)(row + 8) * N + col) =
                        __floats2half2_rn(gelu(c2 + bz0), gelu(c3 + bz1));
                }
            }
        }
    }
}

// ---------------------------------------------------------------------------
// Launch
// ---------------------------------------------------------------------------
extern "C" void kernel_launch(void* const* d_in, const int* in_sizes, int n_in,
                              void* d_out, int out_size) {
    const float* x    = (const float*)d_in[0];
    const float* unc  = (const float*)d_in[1];
    const float* Wq   = (const float*)d_in[2];
    const float* Wk   = (const float*)d_in[3];
    const float* Wv   = (const float*)d_in[4];
    const float* Wo   = (const float*)d_in[5];
    const float* bo   = (const float*)d_in[6];
    const float* ln1g = (const float*)d_in[7];
    const float* ln1b = (const float*)d_in[8];
    const float* ln2g = (const float*)d_in[9];
    const float* ln2b = (const float*)d_in[10];
    const float* W1   = (const float*)d_in[11];
    const float* b1   = (const float*)d_in[12];
    const float* W2   = (const float*)d_in[13];
    const float* b2   = (const float*)d_in[14];

    f16 *tmp, *qkv, *attn, *ff, *wqkv, *wo, *w1, *w2;
    float* x2;
    cudaGetSymbolAddress((void**)&tmp, g_tmp);
    cudaGetSymbolAddress((void**)&qkv, g_qkv);
    cudaGetSymbolAddress((void**)&attn, g_attn);
    cudaGetSymbolAddress((void**)&x2, g_x2);
    cudaGetSymbolAddress((void**)&ff, g_ff);
    cudaGetSymbolAddress((void**)&wqkv, g_wqkv);
    cudaGetSymbolAddress((void**)&wo, g_wo);
    cudaGetSymbolAddress((void**)&w1, g_w1);
    cudaGetSymbolAddress((void**)&w2, g_w2);

    cudaFuncSetAttribute(gemm_f16<0>, cudaFuncAttributeMaxDynamicSharedMemorySize, (int)GEMM_SMEM);
    cudaFuncSetAttribute(gemm_f16<1>, cudaFuncAttributeMaxDynamicSharedMemorySize, (int)GEMM_SMEM);
    cudaFuncSetAttribute(gemm_f16<2>, cudaFuncAttributeMaxDynamicSharedMemorySize, (int)GEMM_SMEM);

    int nsm = 148;
    cudaDeviceGetAttribute(&nsm, cudaDevAttrMultiProcessorCount, 0);
    const int PGRID = 2 * nsm;

    transpose_all<<<12288, dim3(32, 8)>>>(Wq, Wk, Wv, Wo, W1, W2, wqkv, wo, w1, w2);

    // tmp = LN1(x)
    ln_kernel<<<TOKENS, 256>>>(x, ln1g, ln1b, tmp);
    // qkv = tmp @ [Wq|Wk|Wv]
    gemm_f16<0><<<PGRID, 256, GEMM_SMEM>>>(
        tmp, wqkv, nullptr, nullptr, qkv, TOKENS, 3 * D, D);
    // per-token attention (tensor-core)
    attn_tc<<<TOKENS / 2, 256>>>(qkv, unc, attn);
    // x2 = x + attn @ Wo + bo
    gemm_f16<1><<<PGRID, 256, GEMM_SMEM>>>(
        attn, wo, bo, x, x2, TOKENS, D, D);
    // tmp = LN2(x2)
    ln_kernel<<<TOKENS, 256>>>(x2, ln2g, ln2b, tmp);
    // ff = gelu(tmp @ W1 + b1)
    gemm_f16<2><<<PGRID, 256, GEMM_SMEM>>>(
        tmp, w1, b1, nullptr, ff, TOKENS, DFF, D);
    // out = x2 + ff @ W2 + b2
    gemm_f16<1><<<PGRID, 256, GEMM_SMEM>>>(
        ff, w2, b2, x2, (float*)d_out, TOKENS, D, DFF);
}